// round 12
// baseline (speedup 1.0000x reference)
#include <cuda_runtime.h>
#include <cuda_fp16.h>
#include <cstdint>

// ============================================================================
// out[m,o] = absmax[o] * sum_i x[m,i]*code[q[o,i]] + bias[o]
// Path: prep (dequant W->fp16, absmax deferred; x->fp16) in ONE kernel,
//       mma.sync m16n8k16 GEMM (fp32 accum), scale+bias epilogue.
// R11: BK 64->128 (two 64-half sub-tiles), STAGES 4->2 (same 192 KB smem).
//      Halves the per-kt barrier count: R10 ncu showed tensor=87.7% with
//      the 12% idle matching the per-2048-cyc CP_WAIT+bar convergence cost.
// ============================================================================

#define M_TOTAL 4096
#define N_TOTAL 16384
#define K_TOTAL 4096

#define BM 128
#define BN 256
#define BKH 64              // halves per sub-tile (128 bytes/row)
#define BK 128              // halves per kt (2 sub-tiles)
#define STAGES 2
#define KT (K_TOTAL / BK)   // 32

#define A_HALF (BM * 128)                    // 16 KB
#define B_HALF (BN * 128)                    // 32 KB
#define A_STAGE (2 * A_HALF)                 // 32 KB
#define B_STAGE (2 * B_HALF)                 // 64 KB
#define SMEM_B_OFF (STAGES * A_STAGE)        // 64 KB
#define SMEM_TOTAL (STAGES * (A_STAGE + B_STAGE))  // 192 KB

__device__ __half g_W[(size_t)N_TOTAL * K_TOTAL];   // 128 MB
__device__ __half g_X[(size_t)M_TOTAL * K_TOTAL];   // 32 MB

// ---------------------------------------------------------------------------
__device__ __forceinline__ uint32_t smem_u32(const void* p) {
    uint32_t a;
    asm("{ .reg .u64 t; cvta.to.shared.u64 t, %1; cvt.u32.u64 %0, t; }"
        : "=r"(a) : "l"(p));
    return a;
}

__device__ __forceinline__ void cp_async16(uint32_t dst, const void* src) {
    asm volatile("cp.async.cg.shared.global [%0], [%1], 16;"
                 :: "r"(dst), "l"(src));
}
#define CP_COMMIT() asm volatile("cp.async.commit_group;" ::: "memory")
#define CP_WAIT(N)  asm volatile("cp.async.wait_group %0;" :: "n"(N) : "memory")

__device__ __forceinline__ void ldsm_x4(uint32_t& r0, uint32_t& r1,
                                        uint32_t& r2, uint32_t& r3, uint32_t addr) {
    asm volatile("ldmatrix.sync.aligned.m8n8.x4.shared.b16 {%0,%1,%2,%3}, [%4];"
                 : "=r"(r0), "=r"(r1), "=r"(r2), "=r"(r3) : "r"(addr));
}

__device__ __forceinline__ void mma16816(float* d, const uint32_t* a,
                                         uint32_t b0, uint32_t b1) {
    asm volatile(
        "mma.sync.aligned.m16n8k16.row.col.f32.f16.f16.f32 "
        "{%0,%1,%2,%3}, {%4,%5,%6,%7}, {%8,%9}, {%0,%1,%2,%3};"
        : "+f"(d[0]), "+f"(d[1]), "+f"(d[2]), "+f"(d[3])
        : "r"(a[0]), "r"(a[1]), "r"(a[2]), "r"(a[3]), "r"(b0), "r"(b1));
}

// XOR swizzle for 128B rows, applied to the FULL column byte offset.
__device__ __forceinline__ uint32_t sw(uint32_t row, uint32_t colByte) {
    return row * 128 + (colByte ^ ((row & 7u) << 4));
}

// ---------------------------------------------------------------------------
// Prep kernel: blocks [0, WBLK): dequant W; blocks [WBLK, WBLK+XBLK): x->fp16.
// ---------------------------------------------------------------------------
#define WBLK 32768
#define XBLK 8192

__global__ void __launch_bounds__(256) prep_kernel(
    const int* __restrict__ q, const float* __restrict__ code,
    const float* __restrict__ x,
    __half* __restrict__ W, __half* __restrict__ X)
{
    if (blockIdx.x < WBLK) {
        __shared__ float s_code[256];
        if (threadIdx.x < 256) s_code[threadIdx.x] = code[threadIdx.x];
        __syncthreads();

        size_t base = ((size_t)blockIdx.x * 256 + threadIdx.x) * 8;
        int4 q0 = __ldcs(reinterpret_cast<const int4*>(q + base));
        int4 q1 = __ldcs(reinterpret_cast<const int4*>(q + base + 4));

        __half h[8];
        h[0] = __float2half(s_code[q0.x]); h[1] = __float2half(s_code[q0.y]);
        h[2] = __float2half(s_code[q0.z]); h[3] = __float2half(s_code[q0.w]);
        h[4] = __float2half(s_code[q1.x]); h[5] = __float2half(s_code[q1.y]);
        h[6] = __float2half(s_code[q1.z]); h[7] = __float2half(s_code[q1.w]);

        __stcs(reinterpret_cast<uint4*>(W + base),
               *reinterpret_cast<uint4*>(h));
    } else {
        size_t base = ((size_t)(blockIdx.x - WBLK) * 256 + threadIdx.x) * 8;
        float4 a = __ldcs(reinterpret_cast<const float4*>(x + base));
        float4 b = __ldcs(reinterpret_cast<const float4*>(x + base + 4));
        __half2 h0 = __floats2half2_rn(a.x, a.y);
        __half2 h1 = __floats2half2_rn(a.z, a.w);
        __half2 h2 = __floats2half2_rn(b.x, b.y);
        __half2 h3 = __floats2half2_rn(b.z, b.w);
        uint4 pk;
        pk.x = *reinterpret_cast<uint32_t*>(&h0);
        pk.y = *reinterpret_cast<uint32_t*>(&h1);
        pk.z = *reinterpret_cast<uint32_t*>(&h2);
        pk.w = *reinterpret_cast<uint32_t*>(&h3);
        *reinterpret_cast<uint4*>(X + base) = pk;   // X re-read soon: keep in L2
    }
}

// ---------------------------------------------------------------------------
// GEMM. 256 threads = 8 warps, warp grid 2(M) x 4(N), warp tile 64x64.
// grid(32 mtiles, 64 ntiles) — mtile fastest: X stays L2-resident.
// ---------------------------------------------------------------------------
__global__ void __launch_bounds__(256, 1)
gemm_kernel(const __half* __restrict__ X, const __half* __restrict__ W,
            const float* __restrict__ absmax, const float* __restrict__ bias,
            float* __restrict__ out)
{
    extern __shared__ char smem[];
    const uint32_t sb = smem_u32(smem);

    const int tid  = threadIdx.x;
    const int lane = tid & 31;
    const int wid  = tid >> 5;
    const int wm   = wid >> 2;
    const int wn   = wid & 3;
    const int mtile = blockIdx.x;       // 0..31 (fastest)
    const int ntile = blockIdx.y;       // 0..63

    const size_t m_base = (size_t)mtile * BM;
    const size_t n_base = (size_t)ntile * BN;

    // --- stage loader: per kt, 2 halves; per half A 4 passes, B 8 passes ---
    const int row0 = tid >> 3;          // 0..31
    const int c16  = tid & 7;           // 0..7
    const uint32_t dOff0 = sw((uint32_t)row0, (uint32_t)c16 * 16);
    const __half* gAb = X + (m_base + row0) * K_TOTAL + c16 * 8;
    const __half* gBb = W + (n_base + row0) * K_TOTAL + c16 * 8;

    auto load_stage = [&](int stage, int kt) {
        const size_t ko = (size_t)kt * BK;
        #pragma unroll
        for (int h = 0; h < 2; h++) {
            const uint32_t sa = sb + stage * A_STAGE + h * A_HALF + dOff0;
            const uint32_t sB = sb + SMEM_B_OFF + stage * B_STAGE + h * B_HALF + dOff0;
            const size_t kh = ko + h * BKH;
            #pragma unroll
            for (int p = 0; p < 4; p++)
                cp_async16(sa + p * (32 * 128), gAb + (size_t)p * 32 * K_TOTAL + kh);
            #pragma unroll
            for (int p = 0; p < 8; p++)
                cp_async16(sB + p * (32 * 128), gBb + (size_t)p * 32 * K_TOTAL + kh);
        }
    };

    // --- ldmatrix addressing (row%8 == lane&7 for both operands) ---
    const uint32_t xmask = (uint32_t)(lane & 7) << 4;
    uint32_t aRow[4];
    const uint32_t aCb = (uint32_t)(lane >> 4) * 16;
    {
        const int r = wm * 64 + (lane & 15);
        #pragma unroll
        for (int i = 0; i < 4; i++)
            aRow[i] = (uint32_t)(r + i * 16) * 128;
    }
    uint32_t bRow[4];
    const uint32_t bCb = (uint32_t)((lane >> 3) & 1) * 16;
    {
        const int g = lane >> 3;
        const int r = wn * 64 + (g >> 1) * 8 + (lane & 7);
        #pragma unroll
        for (int j = 0; j < 4; j++)
            bRow[j] = (uint32_t)(r + j * 16) * 128;
    }

    uint32_t a[2][4][4];
    uint32_t b[2][8][2];

    // frag loader: buffer bi <- (sub-tile bases, ks within sub-tile 0..3)
    auto ld_frags = [&](int bi, uint32_t aBase, uint32_t bBase, int ks) {
        const uint32_t aCol = (aCb + ks * 32) ^ xmask;
        const uint32_t bCol = (bCb + ks * 32) ^ xmask;
        #pragma unroll
        for (int i = 0; i < 4; i++)
            ldsm_x4(a[bi][i][0], a[bi][i][1], a[bi][i][2], a[bi][i][3],
                    aBase + aRow[i] + aCol);
        #pragma unroll
        for (int jj = 0; jj < 4; jj++) {
            uint32_t r0, r1, r2, r3;
            ldsm_x4(r0, r1, r2, r3, bBase + bRow[jj] + bCol);
            b[bi][2 * jj][0] = r0;     b[bi][2 * jj][1] = r1;
            b[bi][2 * jj + 1][0] = r2; b[bi][2 * jj + 1][1] = r3;
        }
    };

    float acc[4][8][4];
    #pragma unroll
    for (int i = 0; i < 4; i++)
        #pragma unroll
        for (int j = 0; j < 8; j++)
            #pragma unroll
            for (int e = 0; e < 4; e++) acc[i][j][e] = 0.f;

    // --- prologue: load stage 0, preload frags (stage0, half0, ks0) ---
    load_stage(0, 0); CP_COMMIT();
    CP_WAIT(0);
    __syncthreads();
    ld_frags(0, sb, sb + SMEM_B_OFF, 0);

    // --- mainloop: 32 kt, ONE barrier per kt (4096 MMA cyc between) ---
    #pragma unroll 1
    for (int ktg = 0; ktg < KT / 2; ktg++) {
        #pragma unroll
        for (int s = 0; s < 2; s++) {
            const int kt = ktg * 2 + s;

            // load the OTHER stage for kt+1 (its readers finished last kt)
            if (kt + 1 < KT) {
                load_stage(s ^ 1, kt + 1);
                CP_COMMIT();
            }

            const uint32_t aS = sb + s * A_STAGE;
            const uint32_t bS = sb + SMEM_B_OFF + s * B_STAGE;

            #pragma unroll
            for (int k8 = 0; k8 < 8; k8++) {
                if (k8 < 7) {
                    const int nk = k8 + 1;
                    ld_frags(nk & 1,
                             aS + (nk >> 2) * A_HALF,
                             bS + (nk >> 2) * B_HALF,
                             nk & 3);
                }
                const int cur = k8 & 1;
                #pragma unroll
                for (int i = 0; i < 4; i++)
                    #pragma unroll
                    for (int j = 0; j < 8; j++)
                        mma16816(acc[i][j], a[cur][i], b[cur][j][0], b[cur][j][1]);
            }

            CP_WAIT(0);
            __syncthreads();

            // prefetch (next stage, half0, ks0) -> buf0
            if (kt + 1 < KT) {
                const int ns = s ^ 1;
                ld_frags(0, sb + ns * A_STAGE,
                         sb + SMEM_B_OFF + ns * B_STAGE, 0);
            }
        }
    }

    // --- epilogue: out = acc * absmax[n] + bias[n], streaming stores ---
    const int r  = lane >> 2;
    const int c2 = (lane & 3) * 2;
    #pragma unroll
    for (int j = 0; j < 8; j++) {
        const size_t n0 = n_base + wn * 64 + j * 8 + c2;
        const float am0 = __ldg(absmax + n0), am1 = __ldg(absmax + n0 + 1);
        const float bs0 = __ldg(bias + n0),   bs1 = __ldg(bias + n0 + 1);
        #pragma unroll
        for (int i = 0; i < 4; i++) {
            const size_t m0 = m_base + wm * 64 + i * 16 + r;
            float2 v0, v1;
            v0.x = fmaf(acc[i][j][0], am0, bs0);
            v0.y = fmaf(acc[i][j][1], am1, bs1);
            v1.x = fmaf(acc[i][j][2], am0, bs0);
            v1.y = fmaf(acc[i][j][3], am1, bs1);
            __stcs(reinterpret_cast<float2*>(out + m0 * N_TOTAL + n0), v0);
            __stcs(reinterpret_cast<float2*>(out + (m0 + 8) * N_TOTAL + n0), v1);
        }
    }
}

// ---------------------------------------------------------------------------
extern "C" void kernel_launch(void* const* d_in, const int* in_sizes, int n_in,
                              void* d_out, int out_size)
{
    const float* x      = (const float*)d_in[0];
    const int*   qw     = (const int*)  d_in[1];
    const float* absmax = (const float*)d_in[2];
    const float* code   = (const float*)d_in[3];
    const float* bias   = (const float*)d_in[4];
    float* out = (float*)d_out;

    void *pW = nullptr, *pX = nullptr;
    cudaGetSymbolAddress(&pW, g_W);
    cudaGetSymbolAddress(&pX, g_X);

    prep_kernel<<<WBLK + XBLK, 256>>>(qw, code, x, (__half*)pW, (__half*)pX);

    cudaFuncSetAttribute(gemm_kernel, cudaFuncAttributeMaxDynamicSharedMemorySize,
                         SMEM_TOTAL);
    dim3 grid(M_TOTAL / BM, N_TOTAL / BN);   // (32, 64) — mtile fastest
    gemm_kernel<<<grid, 256, SMEM_TOTAL>>>((const __half*)pX, (const __half*)pW,
                                           absmax, bias, out);
}

// round 13
// speedup vs baseline: 1.0603x; 1.0603x over previous
#include <cuda_runtime.h>
#include <cuda_fp16.h>
#include <cstdint>

// ============================================================================
// out[m,o] = absmax[o] * sum_i x[m,i]*code[q[o,i]] + bias[o]
// Path: prep (dequant W->fp16, absmax deferred; x->fp16) in ONE kernel,
//       mma.sync m16n8k16 GEMM (fp32 accum), scale+bias epilogue.
// R13: 2 CTAs/SM. CTA = 128 thr (2x2 warps, warp tile 64x64), tile 128x128,
//      3 stages x 32KB = 96KB smem/CTA. R10 showed tensor=87.7% with the
//      idle = per-kt barrier convergence; a co-resident CTA fills those gaps.
//      (R11's 2-stage BK=128 regressed: CP_WAIT(0) exposed load jitter.)
// ============================================================================

#define M_TOTAL 4096
#define N_TOTAL 16384
#define K_TOTAL 4096

#define BM 128
#define BN 128
#define BK 64               // halves per k-tile (128 bytes/row)
#define STAGES 3
#define KT (K_TOTAL / BK)   // 64

#define A_TILE_BYTES (BM * 128)              // 16 KB
#define B_TILE_BYTES (BN * 128)              // 16 KB
#define SMEM_B_OFF   (STAGES * A_TILE_BYTES) // 48 KB
#define SMEM_TOTAL   (STAGES * (A_TILE_BYTES + B_TILE_BYTES))  // 96 KB

__device__ __half g_W[(size_t)N_TOTAL * K_TOTAL];   // 128 MB
__device__ __half g_X[(size_t)M_TOTAL * K_TOTAL];   // 32 MB

// ---------------------------------------------------------------------------
__device__ __forceinline__ uint32_t smem_u32(const void* p) {
    uint32_t a;
    asm("{ .reg .u64 t; cvta.to.shared.u64 t, %1; cvt.u32.u64 %0, t; }"
        : "=r"(a) : "l"(p));
    return a;
}

__device__ __forceinline__ void cp_async16(uint32_t dst, const void* src) {
    asm volatile("cp.async.cg.shared.global [%0], [%1], 16;"
                 :: "r"(dst), "l"(src));
}
#define CP_COMMIT() asm volatile("cp.async.commit_group;" ::: "memory")
#define CP_WAIT(N)  asm volatile("cp.async.wait_group %0;" :: "n"(N) : "memory")

__device__ __forceinline__ void ldsm_x4(uint32_t& r0, uint32_t& r1,
                                        uint32_t& r2, uint32_t& r3, uint32_t addr) {
    asm volatile("ldmatrix.sync.aligned.m8n8.x4.shared.b16 {%0,%1,%2,%3}, [%4];"
                 : "=r"(r0), "=r"(r1), "=r"(r2), "=r"(r3) : "r"(addr));
}

__device__ __forceinline__ void mma16816(float* d, const uint32_t* a,
                                         uint32_t b0, uint32_t b1) {
    asm volatile(
        "mma.sync.aligned.m16n8k16.row.col.f32.f16.f16.f32 "
        "{%0,%1,%2,%3}, {%4,%5,%6,%7}, {%8,%9}, {%0,%1,%2,%3};"
        : "+f"(d[0]), "+f"(d[1]), "+f"(d[2]), "+f"(d[3])
        : "r"(a[0]), "r"(a[1]), "r"(a[2]), "r"(a[3]), "r"(b0), "r"(b1));
}

// XOR swizzle for 128B rows, applied to the FULL column byte offset.
__device__ __forceinline__ uint32_t sw(uint32_t row, uint32_t colByte) {
    return row * 128 + (colByte ^ ((row & 7u) << 4));
}

// ---------------------------------------------------------------------------
// Prep kernel: blocks [0, WBLK): dequant W; blocks [WBLK, WBLK+XBLK): x->fp16.
// ---------------------------------------------------------------------------
#define WBLK 32768
#define XBLK 8192

__global__ void __launch_bounds__(256) prep_kernel(
    const int* __restrict__ q, const float* __restrict__ code,
    const float* __restrict__ x,
    __half* __restrict__ W, __half* __restrict__ X)
{
    if (blockIdx.x < WBLK) {
        __shared__ float s_code[256];
        if (threadIdx.x < 256) s_code[threadIdx.x] = code[threadIdx.x];
        __syncthreads();

        size_t base = ((size_t)blockIdx.x * 256 + threadIdx.x) * 8;
        int4 q0 = __ldcs(reinterpret_cast<const int4*>(q + base));
        int4 q1 = __ldcs(reinterpret_cast<const int4*>(q + base + 4));

        __half h[8];
        h[0] = __float2half(s_code[q0.x]); h[1] = __float2half(s_code[q0.y]);
        h[2] = __float2half(s_code[q0.z]); h[3] = __float2half(s_code[q0.w]);
        h[4] = __float2half(s_code[q1.x]); h[5] = __float2half(s_code[q1.y]);
        h[6] = __float2half(s_code[q1.z]); h[7] = __float2half(s_code[q1.w]);

        __stcs(reinterpret_cast<uint4*>(W + base),
               *reinterpret_cast<uint4*>(h));
    } else {
        size_t base = ((size_t)(blockIdx.x - WBLK) * 256 + threadIdx.x) * 8;
        float4 a = __ldcs(reinterpret_cast<const float4*>(x + base));
        float4 b = __ldcs(reinterpret_cast<const float4*>(x + base + 4));
        __half2 h0 = __floats2half2_rn(a.x, a.y);
        __half2 h1 = __floats2half2_rn(a.z, a.w);
        __half2 h2 = __floats2half2_rn(b.x, b.y);
        __half2 h3 = __floats2half2_rn(b.z, b.w);
        uint4 pk;
        pk.x = *reinterpret_cast<uint32_t*>(&h0);
        pk.y = *reinterpret_cast<uint32_t*>(&h1);
        pk.z = *reinterpret_cast<uint32_t*>(&h2);
        pk.w = *reinterpret_cast<uint32_t*>(&h3);
        *reinterpret_cast<uint4*>(X + base) = pk;   // X re-read soon: keep in L2
    }
}

// ---------------------------------------------------------------------------
// GEMM. 128 threads = 4 warps, warp grid 2(M) x 2(N), warp tile 64x64.
// CTA tile 128x128, 3-stage cp.async pipeline, 2 CTAs/SM.
// grid(32 mtiles, 128 ntiles) — mtile fastest: X stays L2-resident.
// ---------------------------------------------------------------------------
__global__ void __launch_bounds__(128, 2)
gemm_kernel(const __half* __restrict__ X, const __half* __restrict__ W,
            const float* __restrict__ absmax, const float* __restrict__ bias,
            float* __restrict__ out)
{
    extern __shared__ char smem[];
    const uint32_t sb = smem_u32(smem);

    const int tid  = threadIdx.x;
    const int lane = tid & 31;
    const int wid  = tid >> 5;          // 0..3
    const int wm   = wid >> 1;          // 0..1 (M)
    const int wn   = wid & 1;           // 0..1 (N)
    const int mtile = blockIdx.x;       // 0..31 (fastest)
    const int ntile = blockIdx.y;       // 0..127

    const size_t m_base = (size_t)mtile * BM;
    const size_t n_base = (size_t)ntile * BN;

    // --- stage loader: 128 rows x 8 chunks per tile; 128 threads ->
    //     16 rows/pass x 8 passes, 1 chunk each, per operand.
    const int row0 = tid >> 3;          // 0..15
    const int c16  = tid & 7;           // 0..7
    // (row0 + 16p) & 7 == row0 & 7 -> same swizzle offset every pass
    const uint32_t dOff0 = sw((uint32_t)row0, (uint32_t)c16 * 16);
    const __half* gAb = X + (m_base + row0) * K_TOTAL + c16 * 8;
    const __half* gBb = W + (n_base + row0) * K_TOTAL + c16 * 8;

    auto load_stage = [&](int stage, int kt) {
        const uint32_t sa = sb + stage * A_TILE_BYTES + dOff0;
        const uint32_t sB = sb + SMEM_B_OFF + stage * B_TILE_BYTES + dOff0;
        const size_t ko = (size_t)kt * BK;
        #pragma unroll
        for (int p = 0; p < 8; p++)
            cp_async16(sa + p * (16 * 128), gAb + (size_t)p * 16 * K_TOTAL + ko);
        #pragma unroll
        for (int p = 0; p < 8; p++)
            cp_async16(sB + p * (16 * 128), gBb + (size_t)p * 16 * K_TOTAL + ko);
    };

    // --- ldmatrix addressing (row%8 == lane&7 for both operands) ---
    const uint32_t xmask = (uint32_t)(lane & 7) << 4;
    uint32_t aRow[4];
    const uint32_t aCb = (uint32_t)(lane >> 4) * 16;
    {
        const int r = wm * 64 + (lane & 15);
        #pragma unroll
        for (int i = 0; i < 4; i++)
            aRow[i] = (uint32_t)(r + i * 16) * 128;
    }
    uint32_t bRow[4];
    const uint32_t bCb = (uint32_t)((lane >> 3) & 1) * 16;
    {
        const int g = lane >> 3;
        const int r = wn * 64 + (g >> 1) * 8 + (lane & 7);
        #pragma unroll
        for (int j = 0; j < 4; j++)
            bRow[j] = (uint32_t)(r + j * 16) * 128;
    }

    uint32_t a[2][4][4];
    uint32_t b[2][8][2];

    auto ld_frags = [&](int bi, uint32_t aBase, uint32_t bBase, int ks) {
        const uint32_t aCol = (aCb + ks * 32) ^ xmask;
        const uint32_t bCol = (bCb + ks * 32) ^ xmask;
        #pragma unroll
        for (int i = 0; i < 4; i++)
            ldsm_x4(a[bi][i][0], a[bi][i][1], a[bi][i][2], a[bi][i][3],
                    aBase + aRow[i] + aCol);
        #pragma unroll
        for (int jj = 0; jj < 4; jj++) {
            uint32_t r0, r1, r2, r3;
            ldsm_x4(r0, r1, r2, r3, bBase + bRow[jj] + bCol);
            b[bi][2 * jj][0] = r0;     b[bi][2 * jj][1] = r1;
            b[bi][2 * jj + 1][0] = r2; b[bi][2 * jj + 1][1] = r3;
        }
    };

    float acc[4][8][4];
    #pragma unroll
    for (int i = 0; i < 4; i++)
        #pragma unroll
        for (int j = 0; j < 8; j++)
            #pragma unroll
            for (int e = 0; e < 4; e++) acc[i][j][e] = 0.f;

    // --- prologue: fill 2 stages, preload frags (stage0, ks0) -> buf0 ---
    load_stage(0, 0); CP_COMMIT();
    load_stage(1, 1); CP_COMMIT();
    CP_WAIT(STAGES - 2);
    __syncthreads();
    ld_frags(0, sb, sb + SMEM_B_OFF, 0);

    // --- mainloop: ONE barrier per kt; frags double-buffered ---
    int cs = 0;                 // stage holding kt's data
    int ls = STAGES - 1;        // stage slot to load next
    #pragma unroll 1
    for (int kt = 0; kt < KT; kt++) {
        if (kt + STAGES - 1 < KT) {
            load_stage(ls, kt + STAGES - 1);
            CP_COMMIT();
        }
        ls = (ls + 1 == STAGES) ? 0 : ls + 1;

        const uint32_t aBase = sb + cs * A_TILE_BYTES;
        const uint32_t bBase = sb + SMEM_B_OFF + cs * B_TILE_BYTES;

        #pragma unroll
        for (int ks = 0; ks < 4; ks++) {
            if (ks < 3)
                ld_frags((ks + 1) & 1, aBase, bBase, ks + 1);
            const int cur = ks & 1;
            #pragma unroll
            for (int i = 0; i < 4; i++)
                #pragma unroll
                for (int j = 0; j < 8; j++)
                    mma16816(acc[i][j], a[cur][i], b[cur][j][0], b[cur][j][1]);
        }

        CP_WAIT(STAGES - 2);
        __syncthreads();

        cs = (cs + 1 == STAGES) ? 0 : cs + 1;
        if (kt + 1 < KT)
            ld_frags(0, sb + cs * A_TILE_BYTES,
                     sb + SMEM_B_OFF + cs * B_TILE_BYTES, 0);
    }

    // --- epilogue: out = acc * absmax[n] + bias[n], streaming stores ---
    const int r  = lane >> 2;
    const int c2 = (lane & 3) * 2;
    #pragma unroll
    for (int j = 0; j < 8; j++) {
        const size_t n0 = n_base + wn * 64 + j * 8 + c2;
        const float am0 = __ldg(absmax + n0), am1 = __ldg(absmax + n0 + 1);
        const float bs0 = __ldg(bias + n0),   bs1 = __ldg(bias + n0 + 1);
        #pragma unroll
        for (int i = 0; i < 4; i++) {
            const size_t m0 = m_base + wm * 64 + i * 16 + r;
            float2 v0, v1;
            v0.x = fmaf(acc[i][j][0], am0, bs0);
            v0.y = fmaf(acc[i][j][1], am1, bs1);
            v1.x = fmaf(acc[i][j][2], am0, bs0);
            v1.y = fmaf(acc[i][j][3], am1, bs1);
            __stcs(reinterpret_cast<float2*>(out + m0 * N_TOTAL + n0), v0);
            __stcs(reinterpret_cast<float2*>(out + (m0 + 8) * N_TOTAL + n0), v1);
        }
    }
}

// ---------------------------------------------------------------------------
extern "C" void kernel_launch(void* const* d_in, const int* in_sizes, int n_in,
                              void* d_out, int out_size)
{
    const float* x      = (const float*)d_in[0];
    const int*   qw     = (const int*)  d_in[1];
    const float* absmax = (const float*)d_in[2];
    const float* code   = (const float*)d_in[3];
    const float* bias   = (const float*)d_in[4];
    float* out = (float*)d_out;

    void *pW = nullptr, *pX = nullptr;
    cudaGetSymbolAddress(&pW, g_W);
    cudaGetSymbolAddress(&pX, g_X);

    prep_kernel<<<WBLK + XBLK, 256>>>(qw, code, x, (__half*)pW, (__half*)pX);

    cudaFuncSetAttribute(gemm_kernel, cudaFuncAttributeMaxDynamicSharedMemorySize,
                         SMEM_TOTAL);
    dim3 grid(M_TOTAL / BM, N_TOTAL / BN);   // (32, 128) — mtile fastest
    gemm_kernel<<<grid, 128, SMEM_TOTAL>>>((const __half*)pX, (const __half*)pW,
                                           absmax, bias, out);
}